// round 7
// baseline (speedup 1.0000x reference)
#include <cuda_runtime.h>

// out[r,c] = x[r,c] * scale[c],  scale[c] = (u[c] >= 0.1f) ? vec[c]/0.9f : 0
// x: [131072, 1024] fp32. Pure HBM stream: 512 MB read + 512 MB write.
// Best-measured structure (R1): tiny scale-precompute kernel + streaming kernel
// with plain cached loads. This round: exact-fit grid, both loads front-batched
// (MLP=2), no loop / no bounds check.

#define DEPTH 1024
#define P_DROP 0.1f

__device__ float g_scale[DEPTH];

__global__ void compute_scale_kernel(const float* __restrict__ vec,
                                     const float* __restrict__ u) {
    int c = blockIdx.x * blockDim.x + threadIdx.x;
    if (c < DEPTH) {
        float keep = (u[c] >= P_DROP) ? 1.0f : 0.0f;
        g_scale[c] = keep * vec[c] * (1.0f / (1.0f - P_DROP));
    }
}

// Exact fit: gridDim.x * blockDim.x * 2 == n4. S is a multiple of DEPTH/4,
// so both elements a thread touches share one column-quad -> one scale load.
__global__ void __launch_bounds__(256)
scale_cols_kernel(const float4* __restrict__ x,
                  float4* __restrict__ out) {
    const float4* __restrict__ s4 = reinterpret_cast<const float4*>(g_scale);
    int i = blockIdx.x * blockDim.x + threadIdx.x;
    int S = gridDim.x * blockDim.x;     // 16,777,216 (multiple of 256)

    float4 s  = __ldg(&s4[i & (DEPTH / 4 - 1)]);   // L1-resident, 4 KB set

    float4 a0 = x[i];
    float4 a1 = x[i + S];

    a0.x *= s.x; a0.y *= s.y; a0.z *= s.z; a0.w *= s.w;
    a1.x *= s.x; a1.y *= s.y; a1.z *= s.z; a1.w *= s.w;

    out[i]     = a0;
    out[i + S] = a1;
}

extern "C" void kernel_launch(void* const* d_in, const int* in_sizes, int n_in,
                              void* d_out, int out_size) {
    const float* x   = (const float*)d_in[0];
    const float* vec = (const float*)d_in[1];
    const float* u   = (const float*)d_in[2];
    float* out = (float*)d_out;

    compute_scale_kernel<<<(DEPTH + 255) / 256, 256>>>(vec, u);

    // n4 = out_size/4 = 33,554,432; 65536 blocks * 256 threads * 2 = n4 exactly.
    scale_cols_kernel<<<65536, 256>>>((const float4*)x, (float4*)out);
}

// round 8
// speedup vs baseline: 1.0113x; 1.0113x over previous
#include <cuda_runtime.h>

// out[r,c] = x[r,c] * scale[c],  scale[c] = (u[c] >= 0.1f) ? vec[c]/0.9f : 0
// x: [131072, 1024] fp32. DRAM-pinned stream (512 MB read + 512 MB write),
// measured ceiling ~6.8 TB/s. Single fused kernel to kill the ~4-5us cost of
// the separate scale-precompute graph node; scale setup amortized over 8
// float4 per thread so the fusion overhead inside the stream is ~1/4 of R3's.

#define DEPTH 1024
#define P_DROP 0.1f

__global__ void __launch_bounds__(256)
fused_scale8_kernel(const float4* __restrict__ x,
                    const float4* __restrict__ vec4,
                    const float4* __restrict__ u4,
                    float4* __restrict__ out) {
    int i = blockIdx.x * blockDim.x + threadIdx.x;
    const int S = gridDim.x * blockDim.x;   // 4,194,304 — multiple of 256

    // All 8 elements this thread touches share one column-quad.
    int c4 = i & (DEPTH / 4 - 1);
    float4 vv = __ldg(&vec4[c4]);           // 4 KB set: L1/L2 resident
    float4 uu = __ldg(&u4[c4]);
    const float r = 1.0f / (1.0f - P_DROP);
    float4 s;
    s.x = (uu.x >= P_DROP) ? vv.x * r : 0.0f;
    s.y = (uu.y >= P_DROP) ? vv.y * r : 0.0f;
    s.z = (uu.z >= P_DROP) ? vv.z * r : 0.0f;
    s.w = (uu.w >= P_DROP) ? vv.w * r : 0.0f;

    // Exact fit: 8 iterations, no bounds checks. Pairwise batching keeps
    // MLP>=2 within a modest register budget; ptxas may batch further.
#pragma unroll
    for (int k = 0; k < 8; k += 2) {
        float4 a0 = x[i + k * S];
        float4 a1 = x[i + (k + 1) * S];
        a0.x *= s.x; a0.y *= s.y; a0.z *= s.z; a0.w *= s.w;
        a1.x *= s.x; a1.y *= s.y; a1.z *= s.z; a1.w *= s.w;
        out[i + k * S]       = a0;
        out[i + (k + 1) * S] = a1;
    }
}

extern "C" void kernel_launch(void* const* d_in, const int* in_sizes, int n_in,
                              void* d_out, int out_size) {
    const float* x   = (const float*)d_in[0];
    const float* vec = (const float*)d_in[1];
    const float* u   = (const float*)d_in[2];
    float* out = (float*)d_out;

    // n4 = out_size/4 = 33,554,432; 16384 blocks * 256 threads * 8 = n4 exactly.
    fused_scale8_kernel<<<16384, 256>>>(
        (const float4*)x, (const float4*)vec, (const float4*)u, (float4*)out);
}